// round 7
// baseline (speedup 1.0000x reference)
#include <cuda_runtime.h>
#include <cuda_bf16.h>
#include <math.h>

#define BATCH 4
#define SEQ   512
#define EMB   256
#define HEADS 8
#define HD    32
#define NBUCK 32
#define NTOK  (BATCH*SEQ)          // 2048

// -------- scratch (static device globals; no allocation) --------
__device__ float g_q [BATCH*HEADS*SEQ*HD];     // [b][h][l][d]
__device__ float g_k [BATCH*HEADS*SEQ*HD];
__device__ float g_v [BATCH*HEADS*SEQ*HD];
__device__ float g_qe[BATCH*HEADS*SEQ*4*HD];   // [b][h][l][t][n]
__device__ float g_ve[BATCH*HEADS*SEQ*4*HD];   // [b][h][l][t][m]
__device__ float g_W1c[10*HEADS*HD*HD];        // [c][h][m][n]
__device__ float g_W2c[10*HEADS*HD*HD];        // [c][h][n][m]
__device__ int   g_bucket[1024];
__device__ float g_ctx[BATCH*SEQ*EMB];

__device__ __forceinline__ int cmap(int tq, int tk) {
    return (tq != 0 && tk != 0) ? (tq - 1) * 3 + tk : 0;
}

// -------- 1. mix W1/W2 with softmax(alpha), per (c,h) --------
__global__ void prep_kernel(const float* __restrict__ W1, const float* __restrict__ A1,
                            const float* __restrict__ W2, const float* __restrict__ A2) {
    int c = blockIdx.x >> 3, h = blockIdx.x & 7;
    const float* W = blockIdx.y ? W2 : W1;
    const float* A = blockIdx.y ? A2 : A1;
    float* O = blockIdx.y ? g_W2c : g_W1c;
    float a0 = A[c * 24 + 0 * 8 + h];
    float a1 = A[c * 24 + 1 * 8 + h];
    float a2 = A[c * 24 + 2 * 8 + h];
    float mx = fmaxf(a0, fmaxf(a1, a2));
    float e0 = expf(a0 - mx), e1 = expf(a1 - mx), e2 = expf(a2 - mx);
    float inv = 1.0f / (e0 + e1 + e2);
    e0 *= inv; e1 *= inv; e2 *= inv;
    int mn = threadIdx.x;  // 0..1023
    float w = e0 * W[(0 * 8 + h) * 1024 + mn]
            + e1 * W[(1 * 8 + h) * 1024 + mn]
            + e2 * W[(2 * 8 + h) * 1024 + mn];
    O[(c * 8 + h) * 1024 + mn] = w;
}

// -------- 2. T5 relative-position bucket LUT (indexed by q-k+511) --------
__global__ void bucket_kernel() {
    int i = threadIdx.x;            // 0..1023
    int n = i - 511;                // n = q - k
    int ret = (n < 0) ? 16 : 0;
    n = abs(n);
    int idx;
    if (n < 8) {
        idx = ret + n;
    } else {
        float a = logf((float)n * 0.125f);
        float b = a / 1.6094379124341003f;   // log(40/8)
        int vl = 8 + (int)(b * 8.0f);
        idx = ret + min(vl, 15);
    }
    g_bucket[i] = idx;
}

// -------- 3. per-type projections q/k/v  (grid: token-tile x type x mat) --------
__global__ void __launch_bounds__(256) proj_kernel(const float* __restrict__ x,
                                                   const int* __restrict__ ts,
                                                   const float* __restrict__ Wq,
                                                   const float* __restrict__ Wk,
                                                   const float* __restrict__ Wv) {
    __shared__ float Xc[32][256];
    __shared__ int list[96];
    __shared__ int s_cnt;
    int t0   = blockIdx.x * 96;
    int type = blockIdx.y;
    int mat  = blockIdx.z;
    const float* W = (mat == 0) ? Wq : (mat == 1) ? Wk : Wv;
    float* Out     = (mat == 0) ? g_q : (mat == 1) ? g_k : g_v;
    int tid = threadIdx.x;
    if (tid == 0) {
        int c = 0;
        for (int j = 0; j < 96; j++) {
            int tok = t0 + j;
            if (tok < NTOK && ts[tok] == type) list[c++] = tok;
        }
        s_cnt = c;
    }
    __syncthreads();
    int cnt = s_cnt;
    const float* Wt = W + type * 65536;
    int h = tid >> 5, d = tid & 31;
    for (int c0 = 0; c0 < cnt; c0 += 32) {
        for (int j = 0; j < 32; j++) {
            int li = c0 + j;
            Xc[j][tid] = (li < cnt) ? x[list[li] * 256 + tid] : 0.0f;
        }
        __syncthreads();
        float acc[32];
        #pragma unroll
        for (int j = 0; j < 32; j++) acc[j] = 0.0f;
        for (int e4 = 0; e4 < 64; e4++) {
            float w0 = Wt[(e4 * 4 + 0) * 256 + tid];
            float w1 = Wt[(e4 * 4 + 1) * 256 + tid];
            float w2 = Wt[(e4 * 4 + 2) * 256 + tid];
            float w3 = Wt[(e4 * 4 + 3) * 256 + tid];
            #pragma unroll
            for (int j = 0; j < 32; j++) {
                float4 xv = *reinterpret_cast<const float4*>(&Xc[j][e4 * 4]);
                acc[j] += xv.x * w0 + xv.y * w1 + xv.z * w2 + xv.w * w3;
            }
        }
        for (int j = 0; j < 32; j++) {
            int li = c0 + j;
            if (li >= cnt) break;
            int tok = list[li];
            int b = tok >> 9, l = tok & 511;
            Out[((b * 8 + h) * SEQ + l) * 32 + d] = acc[j];
        }
        __syncthreads();
    }
}

// -------- 4. per-token 4-variant transforms (qe / ve) --------
// qmode=1: dst=qe, Wc=W1c, c=cmap(tok_type, t); contraction dst[n]=sum_m src[m]*W[c][m][n]
// qmode=0: dst=ve, Wc=W2c, c=cmap(t, tok_type); contraction dst[m]=sum_n src[n]*W[c][n][m]
__global__ void __launch_bounds__(128) transform_kernel(const int* __restrict__ ts, int qmode) {
    __shared__ float Ws[10 * 1024];
    __shared__ float buf[32][32];
    __shared__ int tt[32];
    const float* Wc = qmode ? g_W1c : g_W2c;
    const float* src = qmode ? g_q : g_v;
    float* dst = qmode ? g_qe : g_ve;
    int h = blockIdx.y;
    int base = blockIdx.x * 32;       // token tile
    int tid = threadIdx.x;
    for (int i = tid; i < 10240; i += 128)
        Ws[i] = Wc[((i >> 10) * 8 + h) * 1024 + (i & 1023)];
    for (int i = tid; i < 1024; i += 128) {
        int j = i >> 5, m = i & 31;
        int tok = base + j;
        int b = tok >> 9, l = tok & 511;
        buf[j][m] = src[((b * 8 + h) * SEQ + l) * 32 + m];
    }
    if (tid < 32) tt[tid] = ts[base + tid];
    __syncthreads();
    int t = tid >> 5, n = tid & 31;
    for (int j = 0; j < 32; j++) {
        int tj = tt[j];
        int c = qmode ? cmap(tj, t) : cmap(t, tj);
        const float* w = &Ws[c * 1024];
        float acc = 0.0f;
        #pragma unroll
        for (int m = 0; m < 32; m++) acc += buf[j][m] * w[m * 32 + n];
        int tok = base + j;
        int b = tok >> 9, l = tok & 511;
        dst[((b * 8 + h) * SEQ + l) * 128 + tid] = acc;
    }
}

// -------- 5. fused attention: scores + bias + mask + online softmax + ctx --------
__global__ void __launch_bounds__(512) attn_kernel(const float* __restrict__ mask,
                                                   const int* __restrict__ ts,
                                                   const float* __restrict__ rp) {
    __shared__ float k_s[32 * 33];
    __shared__ float ve_s[32 * 128];
    __shared__ float qe_s[16 * 128];
    __shared__ float rp_s[320];
    __shared__ int bk_s[1024];
    __shared__ int tk_s[32];
    __shared__ int tq_s[16];
    int b = blockIdx.z, h = blockIdx.y, q0 = blockIdx.x * 16;
    int bh = b * 8 + h;
    int tid = threadIdx.x;
    for (int i = tid; i < 2048; i += 512) qe_s[i] = g_qe[(bh * SEQ + q0) * 128 + i];
    for (int i = tid; i < 320; i += 512) rp_s[i] = rp[i * 8 + h];
    for (int i = tid; i < 1024; i += 512) bk_s[i] = g_bucket[i];
    if (tid < 16) tq_s[tid] = ts[b * SEQ + q0 + tid];
    __syncthreads();
    int w = tid >> 5, lane = tid & 31;
    int q = q0 + w;
    int tq = tq_s[w];
    float m_run = -INFINITY, l_run = 0.0f, acc = 0.0f;
    const float scale = 0.17677669529663687f;   // 1/sqrt(32)
    for (int kt = 0; kt < 16; kt++) {
        int kbase = kt * 32;
        for (int i = tid; i < 1024; i += 512) {
            int j = i >> 5, d = i & 31;
            k_s[j * 33 + d] = g_k[(bh * SEQ + kbase + j) * 32 + d];
        }
        for (int i = tid; i < 4096; i += 512)
            ve_s[i] = g_ve[(bh * SEQ + kbase) * 128 + i];
        if (tid < 32) tk_s[tid] = ts[b * SEQ + kbase + tid];
        __syncthreads();
        int K = kbase + lane;
        int tk = tk_s[lane];
        const float* qv = &qe_s[w * 128 + tk * 32];
        float dot = 0.0f;
        #pragma unroll
        for (int d = 0; d < 32; d++) dot += qv[d] * k_s[lane * 33 + d];
        int c = (tq != 0 && tk != 0) ? (tq - 1) * 3 + tk : 0;
        float bias = rp_s[c * 32 + bk_s[q - K + 511]];
        float s = dot * scale + bias + mask[(b * SEQ + q) * SEQ + K];
        float tm = s;
        #pragma unroll
        for (int o = 16; o; o >>= 1) tm = fmaxf(tm, __shfl_xor_sync(0xffffffffu, tm, o));
        float newm = fmaxf(m_run, tm);
        float corr = __expf(m_run - newm);
        float p = __expf(s - newm);
        float ps = p;
        #pragma unroll
        for (int o = 16; o; o >>= 1) ps += __shfl_xor_sync(0xffffffffu, ps, o);
        l_run = l_run * corr + ps;
        acc *= corr;
        m_run = newm;
        const float* vb = &ve_s[tq * 32 + lane];
        #pragma unroll
        for (int kk = 0; kk < 32; kk++) {
            float pk = __shfl_sync(0xffffffffu, p, kk);
            acc += pk * vb[kk * 128];
        }
        __syncthreads();
    }
    g_ctx[(b * SEQ + q) * EMB + h * 32 + lane] = acc / l_run;
}

// -------- 6. residual + LayerNorm --------
__global__ void __launch_bounds__(256) ln_kernel(const float* __restrict__ x,
                                                 const float* __restrict__ gamma,
                                                 const float* __restrict__ beta,
                                                 float* __restrict__ out) {
    __shared__ float red[8];
    int row = blockIdx.x, tid = threadIdx.x;
    float v = g_ctx[row * 256 + tid] + x[row * 256 + tid];
    float s = v;
    #pragma unroll
    for (int o = 16; o; o >>= 1) s += __shfl_xor_sync(0xffffffffu, s, o);
    if ((tid & 31) == 0) red[tid >> 5] = s;
    __syncthreads();
    float tot = 0.0f;
    #pragma unroll
    for (int i = 0; i < 8; i++) tot += red[i];
    float mu = tot * (1.0f / 256.0f);
    float d = v - mu;
    float d2 = d * d;
    #pragma unroll
    for (int o = 16; o; o >>= 1) d2 += __shfl_xor_sync(0xffffffffu, d2, o);
    __syncthreads();
    if ((tid & 31) == 0) red[tid >> 5] = d2;
    __syncthreads();
    float var = 0.0f;
    #pragma unroll
    for (int i = 0; i < 8; i++) var += red[i];
    var *= (1.0f / 256.0f);
    out[row * 256 + tid] = d * rsqrtf(var + 1e-12f) * gamma[tid] + beta[tid];
}

extern "C" void kernel_launch(void* const* d_in, const int* in_sizes, int n_in,
                              void* d_out, int out_size) {
    (void)in_sizes; (void)n_in; (void)out_size;
    const float* x     = (const float*)d_in[0];
    const float* mask  = (const float*)d_in[1];
    const int*   ts    = (const int*)  d_in[2];
    const float* Wq    = (const float*)d_in[3];
    const float* Wk    = (const float*)d_in[4];
    const float* Wv    = (const float*)d_in[5];
    const float* W1    = (const float*)d_in[6];
    const float* a1    = (const float*)d_in[7];
    const float* W2    = (const float*)d_in[8];
    const float* a2    = (const float*)d_in[9];
    const float* rp    = (const float*)d_in[10];
    const float* gamma = (const float*)d_in[11];
    const float* beta  = (const float*)d_in[12];
    float* out = (float*)d_out;

    prep_kernel<<<dim3(80, 2), 1024>>>(W1, a1, W2, a2);
    bucket_kernel<<<1, 1024>>>();
    proj_kernel<<<dim3(22, 4, 3), 256>>>(x, ts, Wq, Wk, Wv);
    transform_kernel<<<dim3(64, 8), 128>>>(ts, 1);   // qe
    transform_kernel<<<dim3(64, 8), 128>>>(ts, 0);   // ve
    attn_kernel<<<dim3(32, 8, 4), 512>>>(mask, ts, rp);
    ln_kernel<<<NTOK, 256>>>(x, gamma, beta, out);
}

// round 9
// speedup vs baseline: 1.0017x; 1.0017x over previous
#include <cuda_runtime.h>
#include <cuda_bf16.h>
#include <math.h>

#define BATCH 4
#define SEQ   512
#define EMB   256
#define HEADS 8
#define HD    32
#define NBUCK 32
#define NTOK  (BATCH*SEQ)          // 2048

// -------- scratch (static device globals; no allocation) --------
__device__ float g_q [BATCH*HEADS*SEQ*HD];     // [b][h][l][d]
__device__ float g_k [BATCH*HEADS*SEQ*HD];
__device__ float g_v [BATCH*HEADS*SEQ*HD];
__device__ float g_qe[BATCH*HEADS*SEQ*4*HD];   // [b][h][l][t][n]
__device__ float g_ve[BATCH*HEADS*SEQ*4*HD];   // [b][h][l][t][m]
__device__ float g_W1c[10*HEADS*HD*HD];        // [c][h][m][n]
__device__ float g_W2c[10*HEADS*HD*HD];        // [c][h][n][m]
__device__ int   g_bucket[1024];
__device__ float g_ctx[BATCH*SEQ*EMB];

__device__ __forceinline__ int cmap(int tq, int tk) {
    return (tq != 0 && tk != 0) ? (tq - 1) * 3 + tk : 0;
}

// -------- 1. mix W1/W2 with softmax(alpha), per (c,h) --------
__global__ void prep_kernel(const float* __restrict__ W1, const float* __restrict__ A1,
                            const float* __restrict__ W2, const float* __restrict__ A2) {
    int c = blockIdx.x >> 3, h = blockIdx.x & 7;
    const float* W = blockIdx.y ? W2 : W1;
    const float* A = blockIdx.y ? A2 : A1;
    float* O = blockIdx.y ? g_W2c : g_W1c;
    float a0 = A[c * 24 + 0 * 8 + h];
    float a1 = A[c * 24 + 1 * 8 + h];
    float a2 = A[c * 24 + 2 * 8 + h];
    float mx = fmaxf(a0, fmaxf(a1, a2));
    float e0 = expf(a0 - mx), e1 = expf(a1 - mx), e2 = expf(a2 - mx);
    float inv = 1.0f / (e0 + e1 + e2);
    e0 *= inv; e1 *= inv; e2 *= inv;
    int mn = threadIdx.x;  // 0..1023
    float w = e0 * W[(0 * 8 + h) * 1024 + mn]
            + e1 * W[(1 * 8 + h) * 1024 + mn]
            + e2 * W[(2 * 8 + h) * 1024 + mn];
    O[(c * 8 + h) * 1024 + mn] = w;
}

// -------- 2. T5 relative-position bucket LUT (indexed by q-k+511) --------
__global__ void bucket_kernel() {
    int i = threadIdx.x;            // 0..1023
    int n = i - 511;                // n = q - k
    int ret = (n < 0) ? 16 : 0;
    n = abs(n);
    int idx;
    if (n < 8) {
        idx = ret + n;
    } else {
        float a = logf((float)n * 0.125f);
        float b = a / 1.6094379124341003f;   // log(40/8)
        int vl = 8 + (int)(b * 8.0f);
        idx = ret + min(vl, 15);
    }
    g_bucket[i] = idx;
}

// -------- 3. per-type projections q/k/v  (grid: token-tile x type x mat) --------
__global__ void __launch_bounds__(256) proj_kernel(const float* __restrict__ x,
                                                   const int* __restrict__ ts,
                                                   const float* __restrict__ Wq,
                                                   const float* __restrict__ Wk,
                                                   const float* __restrict__ Wv) {
    __shared__ float Xc[32][256];
    __shared__ int list[96];
    __shared__ int s_cnt;
    int t0   = blockIdx.x * 96;
    int type = blockIdx.y;
    int mat  = blockIdx.z;
    const float* W = (mat == 0) ? Wq : (mat == 1) ? Wk : Wv;
    float* Out     = (mat == 0) ? g_q : (mat == 1) ? g_k : g_v;
    int tid = threadIdx.x;
    if (tid == 0) {
        int c = 0;
        for (int j = 0; j < 96; j++) {
            int tok = t0 + j;
            if (tok < NTOK && ts[tok] == type) list[c++] = tok;
        }
        s_cnt = c;
    }
    __syncthreads();
    int cnt = s_cnt;
    const float* Wt = W + type * 65536;
    int h = tid >> 5, d = tid & 31;
    for (int c0 = 0; c0 < cnt; c0 += 32) {
        for (int j = 0; j < 32; j++) {
            int li = c0 + j;
            Xc[j][tid] = (li < cnt) ? x[list[li] * 256 + tid] : 0.0f;
        }
        __syncthreads();
        float acc[32];
        #pragma unroll
        for (int j = 0; j < 32; j++) acc[j] = 0.0f;
        for (int e4 = 0; e4 < 64; e4++) {
            float w0 = Wt[(e4 * 4 + 0) * 256 + tid];
            float w1 = Wt[(e4 * 4 + 1) * 256 + tid];
            float w2 = Wt[(e4 * 4 + 2) * 256 + tid];
            float w3 = Wt[(e4 * 4 + 3) * 256 + tid];
            #pragma unroll
            for (int j = 0; j < 32; j++) {
                float4 xv = *reinterpret_cast<const float4*>(&Xc[j][e4 * 4]);
                acc[j] += xv.x * w0 + xv.y * w1 + xv.z * w2 + xv.w * w3;
            }
        }
        for (int j = 0; j < 32; j++) {
            int li = c0 + j;
            if (li >= cnt) break;
            int tok = list[li];
            int b = tok >> 9, l = tok & 511;
            Out[((b * 8 + h) * SEQ + l) * 32 + d] = acc[j];
        }
        __syncthreads();
    }
}

// -------- 4. per-token 4-variant transforms (qe / ve) --------
// qmode=1: dst=qe, Wc=W1c, c=cmap(tok_type, t); contraction dst[n]=sum_m src[m]*W[c][m][n]
// qmode=0: dst=ve, Wc=W2c, c=cmap(t, tok_type); contraction dst[m]=sum_n src[n]*W[c][n][m]
__global__ void __launch_bounds__(128) transform_kernel(const int* __restrict__ ts, int qmode) {
    __shared__ float Ws[10 * 1024];
    __shared__ float buf[32][32];
    __shared__ int tt[32];
    const float* Wc = qmode ? g_W1c : g_W2c;
    const float* src = qmode ? g_q : g_v;
    float* dst = qmode ? g_qe : g_ve;
    int h = blockIdx.y;
    int base = blockIdx.x * 32;       // token tile
    int tid = threadIdx.x;
    for (int i = tid; i < 10240; i += 128)
        Ws[i] = Wc[((i >> 10) * 8 + h) * 1024 + (i & 1023)];
    for (int i = tid; i < 1024; i += 128) {
        int j = i >> 5, m = i & 31;
        int tok = base + j;
        int b = tok >> 9, l = tok & 511;
        buf[j][m] = src[((b * 8 + h) * SEQ + l) * 32 + m];
    }
    if (tid < 32) tt[tid] = ts[base + tid];
    __syncthreads();
    int t = tid >> 5, n = tid & 31;
    for (int j = 0; j < 32; j++) {
        int tj = tt[j];
        int c = qmode ? cmap(tj, t) : cmap(t, tj);
        const float* w = &Ws[c * 1024];
        float acc = 0.0f;
        #pragma unroll
        for (int m = 0; m < 32; m++) acc += buf[j][m] * w[m * 32 + n];
        int tok = base + j;
        int b = tok >> 9, l = tok & 511;
        dst[((b * 8 + h) * SEQ + l) * 128 + tid] = acc;
    }
}

// -------- 5. fused attention: scores + bias + mask + online softmax + ctx --------
__global__ void __launch_bounds__(512) attn_kernel(const float* __restrict__ mask,
                                                   const int* __restrict__ ts,
                                                   const float* __restrict__ rp) {
    __shared__ float k_s[32 * 33];
    __shared__ float ve_s[32 * 128];
    __shared__ float qe_s[16 * 128];
    __shared__ float rp_s[320];
    __shared__ int bk_s[1024];
    __shared__ int tk_s[32];
    __shared__ int tq_s[16];
    int b = blockIdx.z, h = blockIdx.y, q0 = blockIdx.x * 16;
    int bh = b * 8 + h;
    int tid = threadIdx.x;
    for (int i = tid; i < 2048; i += 512) qe_s[i] = g_qe[(bh * SEQ + q0) * 128 + i];
    for (int i = tid; i < 320; i += 512) rp_s[i] = rp[i * 8 + h];
    for (int i = tid; i < 1024; i += 512) bk_s[i] = g_bucket[i];
    if (tid < 16) tq_s[tid] = ts[b * SEQ + q0 + tid];
    __syncthreads();
    int w = tid >> 5, lane = tid & 31;
    int q = q0 + w;
    int tq = tq_s[w];
    float m_run = -INFINITY, l_run = 0.0f, acc = 0.0f;
    const float scale = 0.17677669529663687f;   // 1/sqrt(32)
    for (int kt = 0; kt < 16; kt++) {
        int kbase = kt * 32;
        for (int i = tid; i < 1024; i += 512) {
            int j = i >> 5, d = i & 31;
            k_s[j * 33 + d] = g_k[(bh * SEQ + kbase + j) * 32 + d];
        }
        for (int i = tid; i < 4096; i += 512)
            ve_s[i] = g_ve[(bh * SEQ + kbase) * 128 + i];
        if (tid < 32) tk_s[tid] = ts[b * SEQ + kbase + tid];
        __syncthreads();
        int K = kbase + lane;
        int tk = tk_s[lane];
        const float* qv = &qe_s[w * 128 + tk * 32];
        float dot = 0.0f;
        #pragma unroll
        for (int d = 0; d < 32; d++) dot += qv[d] * k_s[lane * 33 + d];
        int c = (tq != 0 && tk != 0) ? (tq - 1) * 3 + tk : 0;
        float bias = rp_s[c * 32 + bk_s[q - K + 511]];
        float s = dot * scale + bias + mask[(b * SEQ + q) * SEQ + K];
        float tm = s;
        #pragma unroll
        for (int o = 16; o; o >>= 1) tm = fmaxf(tm, __shfl_xor_sync(0xffffffffu, tm, o));
        float newm = fmaxf(m_run, tm);
        float corr = __expf(m_run - newm);
        float p = __expf(s - newm);
        float ps = p;
        #pragma unroll
        for (int o = 16; o; o >>= 1) ps += __shfl_xor_sync(0xffffffffu, ps, o);
        l_run = l_run * corr + ps;
        acc *= corr;
        m_run = newm;
        const float* vb = &ve_s[tq * 32 + lane];
        #pragma unroll
        for (int kk = 0; kk < 32; kk++) {
            float pk = __shfl_sync(0xffffffffu, p, kk);
            acc += pk * vb[kk * 128];
        }
        __syncthreads();
    }
    g_ctx[(b * SEQ + q) * EMB + h * 32 + lane] = acc / l_run;
}

// -------- 6. residual + LayerNorm --------
__global__ void __launch_bounds__(256) ln_kernel(const float* __restrict__ x,
                                                 const float* __restrict__ gamma,
                                                 const float* __restrict__ beta,
                                                 float* __restrict__ out) {
    __shared__ float red[8];
    int row = blockIdx.x, tid = threadIdx.x;
    float v = g_ctx[row * 256 + tid] + x[row * 256 + tid];
    float s = v;
    #pragma unroll
    for (int o = 16; o; o >>= 1) s += __shfl_xor_sync(0xffffffffu, s, o);
    if ((tid & 31) == 0) red[tid >> 5] = s;
    __syncthreads();
    float tot = 0.0f;
    #pragma unroll
    for (int i = 0; i < 8; i++) tot += red[i];
    float mu = tot * (1.0f / 256.0f);
    float d = v - mu;
    float d2 = d * d;
    #pragma unroll
    for (int o = 16; o; o >>= 1) d2 += __shfl_xor_sync(0xffffffffu, d2, o);
    __syncthreads();
    if ((tid & 31) == 0) red[tid >> 5] = d2;
    __syncthreads();
    float var = 0.0f;
    #pragma unroll
    for (int i = 0; i < 8; i++) var += red[i];
    var *= (1.0f / 256.0f);
    out[row * 256 + tid] = d * rsqrtf(var + 1e-12f) * gamma[tid] + beta[tid];
}

extern "C" void kernel_launch(void* const* d_in, const int* in_sizes, int n_in,
                              void* d_out, int out_size) {
    (void)in_sizes; (void)n_in; (void)out_size;
    const float* x     = (const float*)d_in[0];
    const float* mask  = (const float*)d_in[1];
    const int*   ts    = (const int*)  d_in[2];
    const float* Wq    = (const float*)d_in[3];
    const float* Wk    = (const float*)d_in[4];
    const float* Wv    = (const float*)d_in[5];
    const float* W1    = (const float*)d_in[6];
    const float* a1    = (const float*)d_in[7];
    const float* W2    = (const float*)d_in[8];
    const float* a2    = (const float*)d_in[9];
    const float* rp    = (const float*)d_in[10];
    const float* gamma = (const float*)d_in[11];
    const float* beta  = (const float*)d_in[12];
    float* out = (float*)d_out;

    prep_kernel<<<dim3(80, 2), 1024>>>(W1, a1, W2, a2);
    bucket_kernel<<<1, 1024>>>();
    proj_kernel<<<dim3(22, 4, 3), 256>>>(x, ts, Wq, Wk, Wv);
    transform_kernel<<<dim3(64, 8), 128>>>(ts, 1);   // qe
    transform_kernel<<<dim3(64, 8), 128>>>(ts, 0);   // ve
    attn_kernel<<<dim3(32, 8, 4), 512>>>(mask, ts, rp);
    ln_kernel<<<NTOK, 256>>>(x, gamma, beta, out);
}

// round 11
// speedup vs baseline: 1.3862x; 1.3839x over previous
#include <cuda_runtime.h>
#include <cuda_bf16.h>
#include <math.h>

#define BATCH 4
#define SEQ   512
#define EMB   256
#define HEADS 8
#define HD    32
#define NTOK  (BATCH*SEQ)          // 2048
#define QPB   64                   // queries per attn block

// -------- scratch (static device globals; no allocation) --------
__device__ float g_q  [BATCH*HEADS*SEQ*HD];       // [bh][l][d]
__device__ float g_k  [BATCH*HEADS*SEQ*HD];
__device__ float g_v  [BATCH*HEADS*SEQ*HD];
__device__ float g_qe [BATCH*HEADS*SEQ*4*HD];     // [bh][l][t][d]
__device__ float g_ve2[BATCH*HEADS*4*HD*SEQ];     // [bh][t][m][l]  (transposed for attn)
__device__ float g_W1c[10*HEADS*HD*HD];           // [c][h][m][n]
__device__ float g_W2c[10*HEADS*HD*HD];
__device__ int   g_bucket[1024];
__device__ int   g_perm[BATCH*SEQ];               // queries sorted by type, per batch
__device__ float g_ctx[BATCH*SEQ*EMB];

__device__ __forceinline__ int cmap(int tq, int tk) {
    return (tq != 0 && tk != 0) ? (tq - 1) * 3 + tk : 0;
}

// -------- 1. mix W1/W2 with softmax(alpha), per (c,h) --------
__global__ void prep_kernel(const float* __restrict__ W1, const float* __restrict__ A1,
                            const float* __restrict__ W2, const float* __restrict__ A2) {
    int c = blockIdx.x >> 3, h = blockIdx.x & 7;
    const float* W = blockIdx.y ? W2 : W1;
    const float* A = blockIdx.y ? A2 : A1;
    float* O = blockIdx.y ? g_W2c : g_W1c;
    float a0 = A[c * 24 + 0 * 8 + h];
    float a1 = A[c * 24 + 1 * 8 + h];
    float a2 = A[c * 24 + 2 * 8 + h];
    float mx = fmaxf(a0, fmaxf(a1, a2));
    float e0 = expf(a0 - mx), e1 = expf(a1 - mx), e2 = expf(a2 - mx);
    float inv = 1.0f / (e0 + e1 + e2);
    e0 *= inv; e1 *= inv; e2 *= inv;
    int mn = threadIdx.x;
    float w = e0 * W[(0 * 8 + h) * 1024 + mn]
            + e1 * W[(1 * 8 + h) * 1024 + mn]
            + e2 * W[(2 * 8 + h) * 1024 + mn];
    O[(c * 8 + h) * 1024 + mn] = w;
}

// -------- 2. T5 relative-position bucket LUT (indexed by q-k+511) --------
__global__ void bucket_kernel() {
    int i = threadIdx.x;
    int n = i - 511;
    int ret = (n < 0) ? 16 : 0;
    n = abs(n);
    int idx;
    if (n < 8) {
        idx = ret + n;
    } else {
        float a = logf((float)n * 0.125f);
        float b = a / 1.6094379124341003f;   // log(40/8)
        int vl = 8 + (int)(b * 8.0f);
        idx = ret + min(vl, 15);
    }
    g_bucket[i] = idx;
}

// -------- 2b. per-batch partition of query indices by type --------
// Ordering within a type is nondeterministic (atomics) but each query's result
// is computed identically regardless of processing order, so output is exact.
__global__ void perm_kernel(const int* __restrict__ ts) {
    __shared__ int cnt[4], off[4], cnt2[4];
    int b = blockIdx.x, tid = threadIdx.x;
    if (tid < 4) { cnt[tid] = 0; cnt2[tid] = 0; }
    __syncthreads();
    int t = ts[b * SEQ + tid];
    atomicAdd(&cnt[t], 1);
    __syncthreads();
    if (tid == 0) {
        off[0] = 0;
        off[1] = cnt[0];
        off[2] = cnt[0] + cnt[1];
        off[3] = cnt[0] + cnt[1] + cnt[2];
    }
    __syncthreads();
    int pos = off[t] + atomicAdd(&cnt2[t], 1);
    g_perm[b * SEQ + pos] = tid;
}

// -------- 3. per-type projections q/k/v --------
__global__ void __launch_bounds__(256) proj_kernel(const float* __restrict__ x,
                                                   const int* __restrict__ ts,
                                                   const float* __restrict__ Wq,
                                                   const float* __restrict__ Wk,
                                                   const float* __restrict__ Wv) {
    __shared__ float Xc[32][256];
    __shared__ int list[96];
    __shared__ int s_cnt;
    int t0   = blockIdx.x * 96;
    int type = blockIdx.y;
    int mat  = blockIdx.z;
    const float* W = (mat == 0) ? Wq : (mat == 1) ? Wk : Wv;
    float* Out     = (mat == 0) ? g_q : (mat == 1) ? g_k : g_v;
    int tid = threadIdx.x;
    if (tid == 0) {
        int c = 0;
        for (int j = 0; j < 96; j++) {
            int tok = t0 + j;
            if (tok < NTOK && ts[tok] == type) list[c++] = tok;
        }
        s_cnt = c;
    }
    __syncthreads();
    int cnt = s_cnt;
    const float* Wt = W + type * 65536;
    int h = tid >> 5, d = tid & 31;
    for (int c0 = 0; c0 < cnt; c0 += 32) {
        for (int j = 0; j < 32; j++) {
            int li = c0 + j;
            Xc[j][tid] = (li < cnt) ? x[list[li] * 256 + tid] : 0.0f;
        }
        __syncthreads();
        float acc[32];
        #pragma unroll
        for (int j = 0; j < 32; j++) acc[j] = 0.0f;
        for (int e4 = 0; e4 < 64; e4++) {
            float w0 = Wt[(e4 * 4 + 0) * 256 + tid];
            float w1 = Wt[(e4 * 4 + 1) * 256 + tid];
            float w2 = Wt[(e4 * 4 + 2) * 256 + tid];
            float w3 = Wt[(e4 * 4 + 3) * 256 + tid];
            #pragma unroll
            for (int j = 0; j < 32; j++) {
                float4 xv = *reinterpret_cast<const float4*>(&Xc[j][e4 * 4]);
                acc[j] += xv.x * w0 + xv.y * w1 + xv.z * w2 + xv.w * w3;
            }
        }
        for (int j = 0; j < 32; j++) {
            int li = c0 + j;
            if (li >= cnt) break;
            int tok = list[li];
            int b = tok >> 9, l = tok & 511;
            Out[((b * 8 + h) * SEQ + l) * 32 + d] = acc[j];
        }
        __syncthreads();
    }
}

// -------- 4. per-token 4-variant transforms (qe / ve2) --------
// qmode=1: dst=g_qe  [bh][l][t*32+n],  c=cmap(tok_type, t)
// qmode=0: dst=g_ve2 [bh][t*32+n][l],  c=cmap(t, tok_type)   (smem-transposed write)
// dynamic smem: Ws 10240 | buf 2048 | out_s 8320 | tt 64  => 20672 floats = 82688 B
__global__ void __launch_bounds__(128) transform2_kernel(const int* __restrict__ ts, int qmode) {
    extern __shared__ float smt[];
    float* Ws    = smt;                 // 10240
    float* buf   = smt + 10240;         // 64 x 32
    float* out_s = smt + 12288;         // 128 x 65
    int*   tt    = (int*)(smt + 20608); // 64
    int h = blockIdx.y;
    int base = blockIdx.x * 64;
    int tid = threadIdx.x;
    const float* Wc  = qmode ? g_W1c : g_W2c;
    const float* src = qmode ? g_q : g_v;
    for (int i = tid; i < 10240; i += 128)
        Ws[i] = Wc[((i >> 10) * 8 + h) * 1024 + (i & 1023)];
    for (int i = tid; i < 2048; i += 128) {
        int j = i >> 5, m = i & 31;
        int tok = base + j;
        int b = tok >> 9, l = tok & 511;
        buf[i] = src[((b * 8 + h) * SEQ + l) * 32 + m];
    }
    if (tid < 64) tt[tid] = ts[base + tid];
    __syncthreads();
    int t = tid >> 5, n = tid & 31;
    for (int j = 0; j < 64; j++) {
        int tj = tt[j];
        int c = qmode ? cmap(tj, t) : cmap(t, tj);
        const float* w  = &Ws[c * 1024 + n];
        const float* bj = &buf[j * 32];
        float a0 = 0.f, a1 = 0.f, a2 = 0.f, a3 = 0.f;
        #pragma unroll
        for (int m = 0; m < 32; m += 4) {
            a0 += bj[m]     * w[m * 32];
            a1 += bj[m + 1] * w[(m + 1) * 32];
            a2 += bj[m + 2] * w[(m + 2) * 32];
            a3 += bj[m + 3] * w[(m + 3) * 32];
        }
        float r = (a0 + a1) + (a2 + a3);
        if (qmode) {
            int tok = base + j;
            int b = tok >> 9, l = tok & 511;
            g_qe[((b * 8 + h) * SEQ + l) * 128 + tid] = r;
        } else {
            out_s[tid * 65 + j] = r;
        }
    }
    if (!qmode) {
        __syncthreads();
        for (int i = tid; i < 8192; i += 128) {
            int row = i >> 6, col = i & 63;
            int tok = base + col;
            int b = tok >> 9, l = tok & 511;
            g_ve2[((b * 8 + h) * 128 + row) * SEQ + l] = out_s[row * 65 + col];
        }
    }
}

// -------- 5. fused attention --------
// Block: 512 thr = 16 warps, 4 queries/warp, 64 queries/block (sorted by type).
// dynamic smem (floats): qe_s 9216 | k_s 1152 | ve_s 4608 | p_s 2048 | rp_s 320
//                        | bk_s 1024(int) | qidx 64 | tq 64 | tk 32  = 18528 fl = 74112 B
__global__ void __launch_bounds__(512, 2) attn_kernel(const float* __restrict__ mask,
                                                      const int* __restrict__ ts,
                                                      const float* __restrict__ rp) {
    extern __shared__ float sma[];
    float* qe_s   = sma;            // [64][4][36]
    float* k_s    = sma + 9216;     // [32][36]
    float* ve_s   = sma + 10368;    // [4][32][36]  (kk contiguous)
    float* p_s    = sma + 14976;    // [64][32]
    float* rp_s   = sma + 17024;    // 320
    int*   bk_s   = (int*)(sma + 17344);  // 1024
    int*   qidx_s = bk_s + 1024;    // 64
    int*   tq_s   = qidx_s + 64;    // 64
    int*   tk_s   = tq_s + 64;      // 32

    int b = blockIdx.z, h = blockIdx.y, q0 = blockIdx.x * QPB;
    int bh = b * 8 + h;
    int tid = threadIdx.x;

    if (tid < QPB) {
        int qi = g_perm[b * SEQ + q0 + tid];
        qidx_s[tid] = qi;
        tq_s[tid] = ts[b * SEQ + qi];
    }
    for (int i = tid; i < 320; i += 512) rp_s[i] = rp[i * 8 + h];
    for (int i = tid; i < 1024; i += 512) bk_s[i] = g_bucket[i];
    __syncthreads();
    for (int i = tid; i < QPB * 128; i += 512) {
        int q = i >> 7, r = i & 127;
        qe_s[(q * 4 + (r >> 5)) * 36 + (r & 31)] = g_qe[(bh * SEQ + qidx_s[q]) * 128 + r];
    }

    int w = tid >> 5, lane = tid & 31;
    int qb = w * 4;
    int tql[4], qix[4];
    #pragma unroll
    for (int q = 0; q < 4; q++) { tql[q] = tq_s[qb + q]; qix[q] = qidx_s[qb + q]; }
    bool fast = (tql[0] == tql[1]) && (tql[1] == tql[2]) && (tql[2] == tql[3]);

    float m_run[4], l_run[4], acc[4];
    #pragma unroll
    for (int q = 0; q < 4; q++) { m_run[q] = -INFINITY; l_run[q] = 0.f; acc[q] = 0.f; }
    const float scale = 0.17677669529663687f;   // 1/sqrt(32)

    for (int kt = 0; kt < 16; kt++) {
        int kbase = kt * 32;
        for (int i = tid; i < 1024; i += 512) {
            int k = i >> 5, d = i & 31;
            k_s[k * 36 + d] = g_k[(bh * SEQ + kbase + k) * 32 + d];
        }
        for (int i = tid; i < 4096; i += 512) {
            int tm = i >> 5, kk = i & 31;
            ve_s[tm * 36 + kk] = g_ve2[(bh * 128 + tm) * SEQ + kbase + kk];
        }
        if (tid < 32) tk_s[tid] = ts[b * SEQ + kbase + tid];
        __syncthreads();

        // ---- scores: lane = key ----
        int tk = tk_s[lane];
        int Kg = kbase + lane;
        float sc[4] = {0.f, 0.f, 0.f, 0.f};
        #pragma unroll
        for (int s = 0; s < 8; s++) {
            float4 k4 = *reinterpret_cast<const float4*>(&k_s[lane * 36 + s * 4]);
            #pragma unroll
            for (int q = 0; q < 4; q++) {
                float4 qv = *reinterpret_cast<const float4*>(&qe_s[((qb + q) * 4 + tk) * 36 + s * 4]);
                sc[q] += qv.x * k4.x + qv.y * k4.y + qv.z * k4.z + qv.w * k4.w;
            }
        }
        float corr[4];
        #pragma unroll
        for (int q = 0; q < 4; q++) {
            int c = (tql[q] != 0 && tk != 0) ? (tql[q] - 1) * 3 + tk : 0;
            float s = sc[q] * scale + rp_s[c * 32 + bk_s[qix[q] - Kg + 511]]
                    + mask[(b * SEQ + qix[q]) * SEQ + Kg];
            float tm_ = s;
            #pragma unroll
            for (int o = 16; o; o >>= 1) tm_ = fmaxf(tm_, __shfl_xor_sync(0xffffffffu, tm_, o));
            float nm = fmaxf(m_run[q], tm_);
            corr[q] = __expf(m_run[q] - nm);
            m_run[q] = nm;
            float p = __expf(s - nm);
            float ps = p;
            #pragma unroll
            for (int o = 16; o; o >>= 1) ps += __shfl_xor_sync(0xffffffffu, ps, o);
            l_run[q] = l_run[q] * corr[q] + ps;
            p_s[(qb + q) * 32 + lane] = p;
        }
        __syncwarp();

        // ---- ctx: lane = output dim m ----
        #pragma unroll
        for (int q = 0; q < 4; q++) acc[q] *= corr[q];
        if (fast) {
            const float* vb = &ve_s[(tql[0] * 32 + lane) * 36];
            #pragma unroll
            for (int s = 0; s < 8; s++) {
                float4 v4 = *reinterpret_cast<const float4*>(&vb[s * 4]);
                #pragma unroll
                for (int q = 0; q < 4; q++) {
                    float4 p4 = *reinterpret_cast<const float4*>(&p_s[(qb + q) * 32 + s * 4]);
                    acc[q] += p4.x * v4.x + p4.y * v4.y + p4.z * v4.z + p4.w * v4.w;
                }
            }
        } else {
            #pragma unroll
            for (int q = 0; q < 4; q++) {
                const float* vb = &ve_s[(tql[q] * 32 + lane) * 36];
                #pragma unroll
                for (int s = 0; s < 8; s++) {
                    float4 v4 = *reinterpret_cast<const float4*>(&vb[s * 4]);
                    float4 p4 = *reinterpret_cast<const float4*>(&p_s[(qb + q) * 32 + s * 4]);
                    acc[q] += p4.x * v4.x + p4.y * v4.y + p4.z * v4.z + p4.w * v4.w;
                }
            }
        }
        __syncthreads();
    }
    #pragma unroll
    for (int q = 0; q < 4; q++)
        g_ctx[(b * SEQ + qix[q]) * EMB + h * 32 + lane] = acc[q] / l_run[q];
}

// -------- 6. residual + LayerNorm --------
__global__ void __launch_bounds__(256) ln_kernel(const float* __restrict__ x,
                                                 const float* __restrict__ gamma,
                                                 const float* __restrict__ beta,
                                                 float* __restrict__ out) {
    __shared__ float red[8];
    int row = blockIdx.x, tid = threadIdx.x;
    float v = g_ctx[row * 256 + tid] + x[row * 256 + tid];
    float s = v;
    #pragma unroll
    for (int o = 16; o; o >>= 1) s += __shfl_xor_sync(0xffffffffu, s, o);
    if ((tid & 31) == 0) red[tid >> 5] = s;
    __syncthreads();
    float tot = 0.0f;
    #pragma unroll
    for (int i = 0; i < 8; i++) tot += red[i];
    float mu = tot * (1.0f / 256.0f);
    float d = v - mu;
    float d2 = d * d;
    #pragma unroll
    for (int o = 16; o; o >>= 1) d2 += __shfl_xor_sync(0xffffffffu, d2, o);
    __syncthreads();
    if ((tid & 31) == 0) red[tid >> 5] = d2;
    __syncthreads();
    float var = 0.0f;
    #pragma unroll
    for (int i = 0; i < 8; i++) var += red[i];
    var *= (1.0f / 256.0f);
    out[row * 256 + tid] = d * rsqrtf(var + 1e-12f) * gamma[tid] + beta[tid];
}

extern "C" void kernel_launch(void* const* d_in, const int* in_sizes, int n_in,
                              void* d_out, int out_size) {
    (void)in_sizes; (void)n_in; (void)out_size;
    const float* x     = (const float*)d_in[0];
    const float* mask  = (const float*)d_in[1];
    const int*   ts    = (const int*)  d_in[2];
    const float* Wq    = (const float*)d_in[3];
    const float* Wk    = (const float*)d_in[4];
    const float* Wv    = (const float*)d_in[5];
    const float* W1    = (const float*)d_in[6];
    const float* a1    = (const float*)d_in[7];
    const float* W2    = (const float*)d_in[8];
    const float* a2    = (const float*)d_in[9];
    const float* rp    = (const float*)d_in[10];
    const float* gamma = (const float*)d_in[11];
    const float* beta  = (const float*)d_in[12];
    float* out = (float*)d_out;

    const int TR_SMEM  = 20672 * 4;   // 82688 B
    const int AT_SMEM  = 18528 * 4;   // 74112 B
    cudaFuncSetAttribute(transform2_kernel, cudaFuncAttributeMaxDynamicSharedMemorySize, TR_SMEM);
    cudaFuncSetAttribute(attn_kernel,       cudaFuncAttributeMaxDynamicSharedMemorySize, AT_SMEM);

    prep_kernel<<<dim3(80, 2), 1024>>>(W1, a1, W2, a2);
    bucket_kernel<<<1, 1024>>>();
    perm_kernel<<<BATCH, 512>>>(ts);
    proj_kernel<<<dim3(22, 4, 3), 256>>>(x, ts, Wq, Wk, Wv);
    transform2_kernel<<<dim3(32, 8), 128, TR_SMEM>>>(ts, 1);   // qe
    transform2_kernel<<<dim3(32, 8), 128, TR_SMEM>>>(ts, 0);   // ve2
    attn_kernel<<<dim3(SEQ / QPB, HEADS, BATCH), 512, AT_SMEM>>>(mask, ts, rp);
    ln_kernel<<<NTOK, 256>>>(x, gamma, beta, out);
}

// round 16
// speedup vs baseline: 1.8507x; 1.3351x over previous
#include <cuda_runtime.h>
#include <cuda_bf16.h>
#include <math.h>

#define BATCH 4
#define SEQ   512
#define EMB   256
#define HEADS 8
#define HD    32
#define NTOK  (BATCH*SEQ)          // 2048
#define QPB   64                   // queries per attn block
#define LCAP  2176                 // sorted+padded token list capacity (2048 + 4*16, rounded)

// -------- scratch (static device globals; no allocation) --------
__device__ float g_q  [BATCH*HEADS*SEQ*HD];       // [bh][l][d]
__device__ float g_k  [BATCH*HEADS*SEQ*HD];
__device__ float g_v  [BATCH*HEADS*SEQ*HD];
__device__ float g_qe [BATCH*HEADS*SEQ*4*HD];     // [bh][l][t][d]
__device__ float g_ve2[BATCH*HEADS*4*HD*SEQ];     // [bh][t][m][l]
__device__ float g_W1c[10*HEADS*HD*HD];           // [c][h][m][n]
__device__ float g_W2c[10*HEADS*HD*HD];
__device__ int   g_bucket[1024];
__device__ int   g_perm[BATCH*SEQ];               // queries sorted by type, per batch
__device__ int   g_list[LCAP];                    // all tokens type-sorted, -1 padded
__device__ float g_ctx[BATCH*SEQ*EMB];

__device__ __forceinline__ int cmap(int tq, int tk) {
    return (tq != 0 && tk != 0) ? (tq - 1) * 3 + tk : 0;
}

// -------- packed fp32x2 helpers --------
__device__ __forceinline__ void ffma2(unsigned long long& d, unsigned long long a, unsigned long long b) {
    asm("fma.rn.f32x2 %0, %1, %2, %0;" : "+l"(d) : "l"(a), "l"(b));
}
__device__ __forceinline__ unsigned long long pack2(float lo, float hi) {
    unsigned long long r;
    asm("mov.b64 %0, {%1, %2};" : "=l"(r) : "f"(lo), "f"(hi));
    return r;
}
__device__ __forceinline__ float hadd2(unsigned long long a) {
    float lo, hi;
    asm("mov.b64 {%0, %1}, %2;" : "=f"(lo), "=f"(hi) : "l"(a));
    return lo + hi;
}
__device__ __forceinline__ void mulsc2(unsigned long long& d, unsigned long long s) {
    asm("mul.rn.f32x2 %0, %0, %1;" : "+l"(d) : "l"(s));
}

// -------- 1. mix W1/W2 with softmax(alpha), per (c,h) --------
__global__ void prep_kernel(const float* __restrict__ W1, const float* __restrict__ A1,
                            const float* __restrict__ W2, const float* __restrict__ A2) {
    int c = blockIdx.x >> 3, h = blockIdx.x & 7;
    const float* W = blockIdx.y ? W2 : W1;
    const float* A = blockIdx.y ? A2 : A1;
    float* O = blockIdx.y ? g_W2c : g_W1c;
    float a0 = A[c * 24 + 0 * 8 + h];
    float a1 = A[c * 24 + 1 * 8 + h];
    float a2 = A[c * 24 + 2 * 8 + h];
    float mx = fmaxf(a0, fmaxf(a1, a2));
    float e0 = expf(a0 - mx), e1 = expf(a1 - mx), e2 = expf(a2 - mx);
    float inv = 1.0f / (e0 + e1 + e2);
    e0 *= inv; e1 *= inv; e2 *= inv;
    int mn = threadIdx.x;
    float w = e0 * W[(0 * 8 + h) * 1024 + mn]
            + e1 * W[(1 * 8 + h) * 1024 + mn]
            + e2 * W[(2 * 8 + h) * 1024 + mn];
    O[(c * 8 + h) * 1024 + mn] = w;
}

// -------- 2. T5 relative-position bucket LUT --------
__global__ void bucket_kernel() {
    int i = threadIdx.x;
    int n = i - 511;
    int ret = (n < 0) ? 16 : 0;
    n = abs(n);
    int idx;
    if (n < 8) {
        idx = ret + n;
    } else {
        float a = logf((float)n * 0.125f);
        float b = a / 1.6094379124341003f;   // log(40/8)
        int vl = 8 + (int)(b * 8.0f);
        idx = ret + min(vl, 15);
    }
    g_bucket[i] = idx;
}

// -------- 2b. per-batch partition of query indices by type (for attn) --------
__global__ void perm_kernel(const int* __restrict__ ts) {
    __shared__ int cnt[4], off[4], cnt2[4];
    int b = blockIdx.x, tid = threadIdx.x;
    if (tid < 4) { cnt[tid] = 0; cnt2[tid] = 0; }
    __syncthreads();
    int t = ts[b * SEQ + tid];
    atomicAdd(&cnt[t], 1);
    __syncthreads();
    if (tid == 0) {
        off[0] = 0;
        off[1] = cnt[0];
        off[2] = cnt[0] + cnt[1];
        off[3] = cnt[0] + cnt[1] + cnt[2];
    }
    __syncthreads();
    int pos = off[t] + atomicAdd(&cnt2[t], 1);
    g_perm[b * SEQ + pos] = tid;
}

// -------- 2c. global type-sort of ALL tokens, padded to 16/type (for proj) --------
__global__ void sort_kernel(const int* __restrict__ ts) {
    __shared__ int cnt[4], base[4], cur[4];
    int tid = threadIdx.x;
    if (tid < 4) { cnt[tid] = 0; cur[tid] = 0; }
    for (int i = tid; i < LCAP; i += 1024) g_list[i] = -1;
    __syncthreads();
    int t0 = ts[tid], t1 = ts[tid + 1024];
    atomicAdd(&cnt[t0], 1);
    atomicAdd(&cnt[t1], 1);
    __syncthreads();
    if (tid == 0) {
        int off = 0;
        for (int t = 0; t < 4; t++) { base[t] = off; off += (cnt[t] + 15) & ~15; }
    }
    __syncthreads();
    int p0 = base[t0] + atomicAdd(&cur[t0], 1);
    g_list[p0] = tid;
    int p1 = base[t1] + atomicAdd(&cur[t1], 1);
    g_list[p1] = tid + 1024;
}

// -------- 3. projections q/k/v over single-type 16-token chunks, packed-e FFMA2 --------
// grid: (LCAP/16 = 136 chunks, 3 mats), block 256 (thread = h*32+d output column)
__global__ void __launch_bounds__(256) proj2_kernel(const float* __restrict__ x,
                                                    const int* __restrict__ ts,
                                                    const float* __restrict__ Wq,
                                                    const float* __restrict__ Wk,
                                                    const float* __restrict__ Wv) {
    __shared__ float Xc[16][256];
    __shared__ int toks[16];
    __shared__ int s_type;
    int c = blockIdx.x, mat = blockIdx.y;
    int tid = threadIdx.x;
    if (tid < 16) toks[tid] = g_list[c * 16 + tid];
    __syncthreads();
    if (toks[0] < 0) return;                 // empty chunk (uniform exit)
    if (tid == 0) s_type = ts[toks[0]];
    #pragma unroll
    for (int j = 0; j < 16; j++) {
        int tok = toks[j];
        Xc[j][tid] = (tok >= 0) ? x[tok * 256 + tid] : 0.0f;
    }
    __syncthreads();
    const float* W = (mat == 0) ? Wq : (mat == 1) ? Wk : Wv;
    float* Out     = (mat == 0) ? g_q : (mat == 1) ? g_k : g_v;
    const float* Wt = W + s_type * 65536;
    unsigned long long acc2[16];
    #pragma unroll
    for (int j = 0; j < 16; j++) acc2[j] = 0ull;
    for (int e4 = 0; e4 < 64; e4++) {
        float w0 = Wt[(e4 * 4 + 0) * 256 + tid];
        float w1 = Wt[(e4 * 4 + 1) * 256 + tid];
        float w2 = Wt[(e4 * 4 + 2) * 256 + tid];
        float w3 = Wt[(e4 * 4 + 3) * 256 + tid];
        unsigned long long w01 = pack2(w0, w1);
        unsigned long long w23 = pack2(w2, w3);
        #pragma unroll
        for (int j = 0; j < 16; j++) {
            ulonglong2 xv = *reinterpret_cast<const ulonglong2*>(&Xc[j][e4 * 4]);
            ffma2(acc2[j], xv.x, w01);
            ffma2(acc2[j], xv.y, w23);
        }
    }
    int h = tid >> 5, d = tid & 31;
    #pragma unroll
    for (int j = 0; j < 16; j++) {
        int tok = toks[j];
        if (tok >= 0) {
            int b = tok >> 9, l = tok & 511;
            Out[((b * 8 + h) * SEQ + l) * 32 + d] = hadd2(acc2[j]);
        }
    }
}

// -------- 4. per-token 4-variant transforms (qe / ve2) --------
__global__ void __launch_bounds__(128) transform2_kernel(const int* __restrict__ ts, int qmode) {
    extern __shared__ float smt[];
    float* Ws    = smt;                 // 10240
    float* buf   = smt + 10240;         // 64 x 32
    float* out_s = smt + 12288;         // 128 x 65
    int*   tt    = (int*)(smt + 20608); // 64
    int h = blockIdx.y;
    int base = blockIdx.x * 64;
    int tid = threadIdx.x;
    const float* Wc  = qmode ? g_W1c : g_W2c;
    const float* src = qmode ? g_q : g_v;
    for (int i = tid; i < 10240; i += 128)
        Ws[i] = Wc[((i >> 10) * 8 + h) * 1024 + (i & 1023)];
    for (int i = tid; i < 2048; i += 128) {
        int j = i >> 5, m = i & 31;
        int tok = base + j;
        int b = tok >> 9, l = tok & 511;
        buf[i] = src[((b * 8 + h) * SEQ + l) * 32 + m];
    }
    if (tid < 64) tt[tid] = ts[base + tid];
    __syncthreads();
    int t = tid >> 5, n = tid & 31;
    for (int j = 0; j < 64; j++) {
        int tj = tt[j];
        int c = qmode ? cmap(tj, t) : cmap(t, tj);
        const float* w  = &Ws[c * 1024 + n];
        const float* bj = &buf[j * 32];
        float a0 = 0.f, a1 = 0.f, a2 = 0.f, a3 = 0.f;
        #pragma unroll
        for (int m = 0; m < 32; m += 4) {
            a0 += bj[m]     * w[m * 32];
            a1 += bj[m + 1] * w[(m + 1) * 32];
            a2 += bj[m + 2] * w[(m + 2) * 32];
            a3 += bj[m + 3] * w[(m + 3) * 32];
        }
        float r = (a0 + a1) + (a2 + a3);
        if (qmode) {
            int tok = base + j;
            int b = tok >> 9, l = tok & 511;
            g_qe[((b * 8 + h) * SEQ + l) * 128 + tid] = r;
        } else {
            out_s[tid * 65 + j] = r;
        }
    }
    if (!qmode) {
        __syncthreads();
        for (int i = tid; i < 8192; i += 128) {
            int row = i >> 6, col = i & 63;
            int tok = base + col;
            int b = tok >> 9, l = tok & 511;
            g_ve2[((b * 8 + h) * 128 + row) * SEQ + l] = out_s[row * 65 + col];
        }
    }
}

// -------- 5. fused attention (FFMA2 score/ctx) --------
__global__ void __launch_bounds__(512, 2) attn_kernel(const float* __restrict__ mask,
                                                      const int* __restrict__ ts,
                                                      const float* __restrict__ rp) {
    extern __shared__ float sma[];
    float* qe_s   = sma;            // [64][4][36]
    float* k_s    = sma + 9216;     // [32][36]
    float* ve_s   = sma + 10368;    // [4][32][36]
    float* p_s    = sma + 14976;    // [64][32]
    float* rp_s   = sma + 17024;    // 320
    int*   bk_s   = (int*)(sma + 17344);  // 1024
    int*   qidx_s = bk_s + 1024;    // 64
    int*   tq_s   = qidx_s + 64;    // 64
    int*   tk_s   = tq_s + 64;      // 32

    int b = blockIdx.z, h = blockIdx.y, q0 = blockIdx.x * QPB;
    int bh = b * 8 + h;
    int tid = threadIdx.x;

    if (tid < QPB) {
        int qi = g_perm[b * SEQ + q0 + tid];
        qidx_s[tid] = qi;
        tq_s[tid] = ts[b * SEQ + qi];
    }
    for (int i = tid; i < 320; i += 512) rp_s[i] = rp[i * 8 + h];
    for (int i = tid; i < 1024; i += 512) bk_s[i] = g_bucket[i];
    __syncthreads();
    for (int i = tid; i < QPB * 128; i += 512) {
        int q = i >> 7, r = i & 127;
        qe_s[(q * 4 + (r >> 5)) * 36 + (r & 31)] = g_qe[(bh * SEQ + qidx_s[q]) * 128 + r];
    }

    int w = tid >> 5, lane = tid & 31;
    int qb = w * 4;
    int tql[4], qix[4];
    #pragma unroll
    for (int q = 0; q < 4; q++) { tql[q] = tq_s[qb + q]; qix[q] = qidx_s[qb + q]; }
    bool fast = (tql[0] == tql[1]) && (tql[1] == tql[2]) && (tql[2] == tql[3]);

    float m_run[4], l_run[4];
    unsigned long long acc2[4];
    #pragma unroll
    for (int q = 0; q < 4; q++) { m_run[q] = -INFINITY; l_run[q] = 0.f; acc2[q] = 0ull; }
    const float scale = 0.17677669529663687f;   // 1/sqrt(32)

    for (int kt = 0; kt < 16; kt++) {
        int kbase = kt * 32;
        for (int i = tid; i < 1024; i += 512) {
            int k = i >> 5, d = i & 31;
            k_s[k * 36 + d] = g_k[(bh * SEQ + kbase + k) * 32 + d];
        }
        for (int i = tid; i < 4096; i += 512) {
            int tm = i >> 5, kk = i & 31;
            ve_s[tm * 36 + kk] = g_ve2[(bh * 128 + tm) * SEQ + kbase + kk];
        }
        if (tid < 32) tk_s[tid] = ts[b * SEQ + kbase + tid];
        __syncthreads();

        // ---- scores: lane = key (packed over d) ----
        int tk = tk_s[lane];
        int Kg = kbase + lane;
        unsigned long long sc2[4] = {0ull, 0ull, 0ull, 0ull};
        #pragma unroll
        for (int s = 0; s < 8; s++) {
            ulonglong2 k2 = *reinterpret_cast<const ulonglong2*>(&k_s[lane * 36 + s * 4]);
            #pragma unroll
            for (int q = 0; q < 4; q++) {
                ulonglong2 q2 = *reinterpret_cast<const ulonglong2*>(
                    &qe_s[((qb + q) * 4 + tk) * 36 + s * 4]);
                ffma2(sc2[q], q2.x, k2.x);
                ffma2(sc2[q], q2.y, k2.y);
            }
        }
        float corr[4];
        #pragma unroll
        for (int q = 0; q < 4; q++) {
            int c = (tql[q] != 0 && tk != 0) ? (tql[q] - 1) * 3 + tk : 0;
            float s = hadd2(sc2[q]) * scale + rp_s[c * 32 + bk_s[qix[q] - Kg + 511]]
                    + mask[(b * SEQ + qix[q]) * SEQ + Kg];
            float tm_ = s;
            #pragma unroll
            for (int o = 16; o; o >>= 1) tm_ = fmaxf(tm_, __shfl_xor_sync(0xffffffffu, tm_, o));
            float nm = fmaxf(m_run[q], tm_);
            corr[q] = __expf(m_run[q] - nm);
            m_run[q] = nm;
            float p = __expf(s - nm);
            float ps = p;
            #pragma unroll
            for (int o = 16; o; o >>= 1) ps += __shfl_xor_sync(0xffffffffu, ps, o);
            l_run[q] = l_run[q] * corr[q] + ps;
            p_s[(qb + q) * 32 + lane] = p;
        }
        __syncwarp();

        // ---- ctx: lane = output dim m (packed over kk) ----
        #pragma unroll
        for (int q = 0; q < 4; q++) mulsc2(acc2[q], pack2(corr[q], corr[q]));
        if (fast) {
            const float* vb = &ve_s[(tql[0] * 32 + lane) * 36];
            #pragma unroll
            for (int s = 0; s < 8; s++) {
                ulonglong2 v2 = *reinterpret_cast<const ulonglong2*>(&vb[s * 4]);
                #pragma unroll
                for (int q = 0; q < 4; q++) {
                    ulonglong2 p2 = *reinterpret_cast<const ulonglong2*>(
                        &p_s[(qb + q) * 32 + s * 4]);
                    ffma2(acc2[q], p2.x, v2.x);
                    ffma2(acc2[q], p2.y, v2.y);
                }
            }
        } else {
            #pragma unroll
            for (int q = 0; q < 4; q++) {
                const float* vb = &ve_s[(tql[q] * 32 + lane) * 36];
                #pragma unroll
                for (int s = 0; s < 8; s++) {
                    ulonglong2 v2 = *reinterpret_cast<const ulonglong2*>(&vb[s * 4]);
                    ulonglong2 p2 = *reinterpret_cast<const ulonglong2*>(
                        &p_s[(qb + q) * 32 + s * 4]);
                    ffma2(acc2[q], p2.x, v2.x);
                    ffma2(acc2[q], p2.y, v2.y);
                }
            }
        }
        __syncthreads();
    }
    #pragma unroll
    for (int q = 0; q < 4; q++)
        g_ctx[(b * SEQ + qix[q]) * EMB + h * 32 + lane] = hadd2(acc2[q]) / l_run[q];
}

// -------- 6. residual + LayerNorm --------
__global__ void __launch_bounds__(256) ln_kernel(const float* __restrict__ x,
                                                 const float* __restrict__ gamma,
                                                 const float* __restrict__ beta,
                                                 float* __restrict__ out) {
    __shared__ float red[8];
    int row = blockIdx.x, tid = threadIdx.x;
    float v = g_ctx[row * 256 + tid] + x[row * 256 + tid];
    float s = v;
    #pragma unroll
    for (int o = 16; o; o >>= 1) s += __shfl_xor_sync(0xffffffffu, s, o);
    if ((tid & 31) == 0) red[tid >> 5] = s;
    __syncthreads();
    float tot = 0.0f;
    #pragma unroll
    for (int i = 0; i < 8; i++) tot += red[i];
    float mu = tot * (1.0f / 256.0f);
    float d = v - mu;
    float d2 = d * d;
    #pragma unroll
    for (int o = 16; o; o >>= 1) d2 += __shfl_xor_sync(0xffffffffu, d2, o);
    __syncthreads();
    if ((tid & 31) == 0) red[tid >> 5] = d2;
    __syncthreads();
    float var = 0.0f;
    #pragma unroll
    for (int i = 0; i < 8; i++) var += red[i];
    var *= (1.0f / 256.0f);
    out[row * 256 + tid] = d * rsqrtf(var + 1e-12f) * gamma[tid] + beta[tid];
}

extern "C" void kernel_launch(void* const* d_in, const int* in_sizes, int n_in,
                              void* d_out, int out_size) {
    (void)in_sizes; (void)n_in; (void)out_size;
    const float* x     = (const float*)d_in[0];
    const float* mask  = (const float*)d_in[1];
    const int*   ts    = (const int*)  d_in[2];
    const float* Wq    = (const float*)d_in[3];
    const float* Wk    = (const float*)d_in[4];
    const float* Wv    = (const float*)d_in[5];
    const float* W1    = (const float*)d_in[6];
    const float* a1    = (const float*)d_in[7];
    const float* W2    = (const float*)d_in[8];
    const float* a2    = (const float*)d_in[9];
    const float* rp    = (const float*)d_in[10];
    const float* gamma = (const float*)d_in[11];
    const float* beta  = (const float*)d_in[12];
    float* out = (float*)d_out;

    const int TR_SMEM  = 20672 * 4;   // 82688 B
    const int AT_SMEM  = 18528 * 4;   // 74112 B
    cudaFuncSetAttribute(transform2_kernel, cudaFuncAttributeMaxDynamicSharedMemorySize, TR_SMEM);
    cudaFuncSetAttribute(attn_kernel,       cudaFuncAttributeMaxDynamicSharedMemorySize, AT_SMEM);

    prep_kernel<<<dim3(80, 2), 1024>>>(W1, a1, W2, a2);
    bucket_kernel<<<1, 1024>>>();
    perm_kernel<<<BATCH, 512>>>(ts);
    sort_kernel<<<1, 1024>>>(ts);
    proj2_kernel<<<dim3(LCAP / 16, 3), 256>>>(x, ts, Wq, Wk, Wv);
    transform2_kernel<<<dim3(32, 8), 128, TR_SMEM>>>(ts, 1);   // qe
    transform2_kernel<<<dim3(32, 8), 128, TR_SMEM>>>(ts, 0);   // ve2
    attn_kernel<<<dim3(SEQ / QPB, HEADS, BATCH), 512, AT_SMEM>>>(mask, ts, rp);
    ln_kernel<<<NTOK, 256>>>(x, gamma, beta, out);
}

// round 17
// speedup vs baseline: 1.8692x; 1.0100x over previous
#include <cuda_runtime.h>
#include <cuda_bf16.h>
#include <math.h>

#define BATCH 4
#define SEQ   512
#define EMB   256
#define HEADS 8
#define HD    32
#define NTOK  (BATCH*SEQ)          // 2048
#define QPB   64                   // queries per attn block
#define LCAP  2176                 // sorted+padded token list capacity

// -------- scratch (static device globals; no allocation) --------
__device__ float g_q  [BATCH*HEADS*SEQ*HD];       // [bh][l][d]
__device__ float g_k  [BATCH*HEADS*SEQ*HD];
__device__ float g_v  [BATCH*HEADS*SEQ*HD];
__device__ float g_qe [BATCH*HEADS*SEQ*4*HD];     // [bh][l][t][d]
__device__ float g_ve2[BATCH*HEADS*4*HD*SEQ];     // [bh][t][m][l]
__device__ float g_W1c[10*HEADS*HD*HD];           // [c][h][m][n]
__device__ float g_W2c[10*HEADS*HD*HD];
__device__ int   g_bucket[1024];
__device__ int   g_perm[BATCH*SEQ];               // queries sorted by type, per batch
__device__ int   g_list[LCAP];                    // all tokens type-sorted, -1 padded
__device__ float g_ctx[BATCH*SEQ*EMB];

__device__ __forceinline__ int cmap(int tq, int tk) {
    return (tq != 0 && tk != 0) ? (tq - 1) * 3 + tk : 0;
}

// -------- packed fp32x2 helpers --------
__device__ __forceinline__ void ffma2(unsigned long long& d, unsigned long long a, unsigned long long b) {
    asm("fma.rn.f32x2 %0, %1, %2, %0;" : "+l"(d) : "l"(a), "l"(b));
}
__device__ __forceinline__ unsigned long long pack2(float lo, float hi) {
    unsigned long long r;
    asm("mov.b64 %0, {%1, %2};" : "=l"(r) : "f"(lo), "f"(hi));
    return r;
}
__device__ __forceinline__ float hadd2(unsigned long long a) {
    float lo, hi;
    asm("mov.b64 {%0, %1}, %2;" : "=f"(lo), "=f"(hi) : "l"(a));
    return lo + hi;
}
__device__ __forceinline__ void mulsc2(unsigned long long& d, unsigned long long s) {
    asm("mul.rn.f32x2 %0, %0, %1;" : "+l"(d) : "l"(s));
}

// -------- 1. fused setup: prep (blocks 0..159) | bucket (160) | perm (161..164) | sort (165) --------
__global__ void __launch_bounds__(1024) setup_kernel(const float* __restrict__ W1,
                                                     const float* __restrict__ A1,
                                                     const float* __restrict__ W2,
                                                     const float* __restrict__ A2,
                                                     const int* __restrict__ ts) {
    int bx = blockIdx.x, tid = threadIdx.x;
    if (bx < 160) {
        // ---- prep: mix W1/W2 with softmax(alpha) per (c,h) ----
        int sel = (bx >= 80);
        int cc = sel ? bx - 80 : bx;
        int c = cc >> 3, h = cc & 7;
        const float* W = sel ? W2 : W1;
        const float* A = sel ? A2 : A1;
        float* O = sel ? g_W2c : g_W1c;
        float a0 = A[c * 24 + 0 * 8 + h];
        float a1 = A[c * 24 + 1 * 8 + h];
        float a2 = A[c * 24 + 2 * 8 + h];
        float mx = fmaxf(a0, fmaxf(a1, a2));
        float e0 = expf(a0 - mx), e1 = expf(a1 - mx), e2 = expf(a2 - mx);
        float inv = 1.0f / (e0 + e1 + e2);
        e0 *= inv; e1 *= inv; e2 *= inv;
        float w = e0 * W[(0 * 8 + h) * 1024 + tid]
                + e1 * W[(1 * 8 + h) * 1024 + tid]
                + e2 * W[(2 * 8 + h) * 1024 + tid];
        O[(c * 8 + h) * 1024 + tid] = w;
    } else if (bx == 160) {
        // ---- T5 bucket LUT ----
        int n = tid - 511;
        int ret = (n < 0) ? 16 : 0;
        n = abs(n);
        int idx;
        if (n < 8) {
            idx = ret + n;
        } else {
            float a = logf((float)n * 0.125f);
            float b = a / 1.6094379124341003f;   // log(40/8)
            int vl = 8 + (int)(b * 8.0f);
            idx = ret + min(vl, 15);
        }
        g_bucket[tid] = idx;
    } else if (bx < 165) {
        // ---- per-batch query permutation by type ----
        __shared__ int cnt[4], off[4], cnt2[4];
        int b = bx - 161;
        if (tid < 4) { cnt[tid] = 0; cnt2[tid] = 0; }
        __syncthreads();
        int t = 0;
        if (tid < 512) { t = ts[b * SEQ + tid]; atomicAdd(&cnt[t], 1); }
        __syncthreads();
        if (tid == 0) {
            off[0] = 0;
            off[1] = cnt[0];
            off[2] = cnt[0] + cnt[1];
            off[3] = cnt[0] + cnt[1] + cnt[2];
        }
        __syncthreads();
        if (tid < 512) {
            int pos = off[t] + atomicAdd(&cnt2[t], 1);
            g_perm[b * SEQ + pos] = tid;
        }
    } else {
        // ---- global type-sort of all tokens, padded to 16/type ----
        __shared__ int cnt[4], base[4], cur[4];
        if (tid < 4) { cnt[tid] = 0; cur[tid] = 0; }
        for (int i = tid; i < LCAP; i += 1024) g_list[i] = -1;
        __syncthreads();
        int t0 = ts[tid], t1 = ts[tid + 1024];
        atomicAdd(&cnt[t0], 1);
        atomicAdd(&cnt[t1], 1);
        __syncthreads();
        if (tid == 0) {
            int off = 0;
            for (int t = 0; t < 4; t++) { base[t] = off; off += (cnt[t] + 15) & ~15; }
        }
        __syncthreads();
        int p0 = base[t0] + atomicAdd(&cur[t0], 1);
        g_list[p0] = tid;
        int p1 = base[t1] + atomicAdd(&cur[t1], 1);
        g_list[p1] = tid + 1024;
    }
}

// -------- 3. projections q/k/v over single-type 16-token chunks, packed-e FFMA2 --------
__global__ void __launch_bounds__(256) proj2_kernel(const float* __restrict__ x,
                                                    const int* __restrict__ ts,
                                                    const float* __restrict__ Wq,
                                                    const float* __restrict__ Wk,
                                                    const float* __restrict__ Wv) {
    __shared__ float Xc[16][256];
    __shared__ int toks[16];
    __shared__ int s_type;
    int c = blockIdx.x, mat = blockIdx.y;
    int tid = threadIdx.x;
    if (tid < 16) toks[tid] = g_list[c * 16 + tid];
    __syncthreads();
    if (toks[0] < 0) return;
    if (tid == 0) s_type = ts[toks[0]];
    #pragma unroll
    for (int j = 0; j < 16; j++) {
        int tok = toks[j];
        Xc[j][tid] = (tok >= 0) ? x[tok * 256 + tid] : 0.0f;
    }
    __syncthreads();
    const float* W = (mat == 0) ? Wq : (mat == 1) ? Wk : Wv;
    float* Out     = (mat == 0) ? g_q : (mat == 1) ? g_k : g_v;
    const float* Wt = W + s_type * 65536;
    unsigned long long acc2[16];
    #pragma unroll
    for (int j = 0; j < 16; j++) acc2[j] = 0ull;
    for (int e4 = 0; e4 < 64; e4++) {
        float w0 = Wt[(e4 * 4 + 0) * 256 + tid];
        float w1 = Wt[(e4 * 4 + 1) * 256 + tid];
        float w2 = Wt[(e4 * 4 + 2) * 256 + tid];
        float w3 = Wt[(e4 * 4 + 3) * 256 + tid];
        unsigned long long w01 = pack2(w0, w1);
        unsigned long long w23 = pack2(w2, w3);
        #pragma unroll
        for (int j = 0; j < 16; j++) {
            ulonglong2 xv = *reinterpret_cast<const ulonglong2*>(&Xc[j][e4 * 4]);
            ffma2(acc2[j], xv.x, w01);
            ffma2(acc2[j], xv.y, w23);
        }
    }
    int h = tid >> 5, d = tid & 31;
    #pragma unroll
    for (int j = 0; j < 16; j++) {
        int tok = toks[j];
        if (tok >= 0) {
            int b = tok >> 9, l = tok & 511;
            Out[((b * 8 + h) * SEQ + l) * 32 + d] = hadd2(acc2[j]);
        }
    }
}

// -------- 4. per-token 4-variant transforms, fused qe/ve2 via blockIdx.z --------
__global__ void __launch_bounds__(128) transform2_kernel(const int* __restrict__ ts) {
    extern __shared__ float smt[];
    float* Ws    = smt;                 // 10240
    float* buf   = smt + 10240;         // 64 x 32
    float* out_s = smt + 12288;         // 128 x 65
    int*   tt    = (int*)(smt + 20608); // 64
    int qmode = (blockIdx.z == 0);      // z=0 -> qe, z=1 -> ve2
    int h = blockIdx.y;
    int base = blockIdx.x * 64;
    int tid = threadIdx.x;
    const float* Wc  = qmode ? g_W1c : g_W2c;
    const float* src = qmode ? g_q : g_v;
    for (int i = tid; i < 10240; i += 128)
        Ws[i] = Wc[((i >> 10) * 8 + h) * 1024 + (i & 1023)];
    for (int i = tid; i < 2048; i += 128) {
        int j = i >> 5, m = i & 31;
        int tok = base + j;
        int b = tok >> 9, l = tok & 511;
        buf[i] = src[((b * 8 + h) * SEQ + l) * 32 + m];
    }
    if (tid < 64) tt[tid] = ts[base + tid];
    __syncthreads();
    int t = tid >> 5, n = tid & 31;
    for (int j = 0; j < 64; j++) {
        int tj = tt[j];
        int c = qmode ? cmap(tj, t) : cmap(t, tj);
        const float* w  = &Ws[c * 1024 + n];
        const float* bj = &buf[j * 32];
        float a0 = 0.f, a1 = 0.f, a2 = 0.f, a3 = 0.f;
        #pragma unroll
        for (int m = 0; m < 32; m += 4) {
            a0 += bj[m]     * w[m * 32];
            a1 += bj[m + 1] * w[(m + 1) * 32];
            a2 += bj[m + 2] * w[(m + 2) * 32];
            a3 += bj[m + 3] * w[(m + 3) * 32];
        }
        float r = (a0 + a1) + (a2 + a3);
        if (qmode) {
            int tok = base + j;
            int b = tok >> 9, l = tok & 511;
            g_qe[((b * 8 + h) * SEQ + l) * 128 + tid] = r;
        } else {
            out_s[tid * 65 + j] = r;
        }
    }
    if (!qmode) {
        __syncthreads();
        for (int i = tid; i < 8192; i += 128) {
            int row = i >> 6, col = i & 63;
            int tok = base + col;
            int b = tok >> 9, l = tok & 511;
            g_ve2[((b * 8 + h) * 128 + row) * SEQ + l] = out_s[row * 65 + col];
        }
    }
}

// -------- 5. fused attention (FFMA2, ve plane-masked) --------
// dyn smem (floats): qe_s 9216 | k_s 1152 | ve_s 4608 | p_s 2048 | rp_s 320
//   | bk_s 1024i | qidx 64i | tq 64i | tk_all 512i | slot 4i | tlist 4i | np 1i (+pad)
//   total 19024 fl = 76096 B
__global__ void __launch_bounds__(512, 2) attn_kernel(const float* __restrict__ mask,
                                                      const int* __restrict__ ts,
                                                      const float* __restrict__ rp) {
    extern __shared__ float sma[];
    float* qe_s   = sma;            // [64][4][36]
    float* k_s    = sma + 9216;     // [32][36]
    float* ve_s   = sma + 10368;    // [4(slots)][32][36]
    float* p_s    = sma + 14976;    // [64][32]
    float* rp_s   = sma + 17024;    // 320
    int*   bk_s   = (int*)(sma + 17344);  // 1024
    int*   qidx_s = bk_s + 1024;    // 64
    int*   tq_s   = qidx_s + 64;    // 64
    int*   tk_all = tq_s + 64;      // 512
    int*   slot_s = tk_all + 512;   // 4
    int*   tlist  = slot_s + 4;     // 4
    int*   np_s   = tlist + 4;      // 1

    int b = blockIdx.z, h = blockIdx.y, q0 = blockIdx.x * QPB;
    int bh = b * 8 + h;
    int tid = threadIdx.x;

    if (tid < QPB) {
        int qi = g_perm[b * SEQ + q0 + tid];
        qidx_s[tid] = qi;
        tq_s[tid] = ts[b * SEQ + qi];
    }
    tk_all[tid] = ts[b * SEQ + tid];          // 512 threads cover SEQ exactly
    for (int i = tid; i < 320; i += 512) rp_s[i] = rp[i * 8 + h];
    for (int i = tid; i < 1024; i += 512) bk_s[i] = g_bucket[i];
    __syncthreads();

    if (tid == 0) {
        int m = 0;
        for (int i = 0; i < QPB; i++) m |= 1 << tq_s[i];
        int np = 0;
        #pragma unroll
        for (int t = 0; t < 4; t++) {
            if (m & (1 << t)) { slot_s[t] = np; tlist[np] = t; np++; }
            else slot_s[t] = -1;
        }
        np_s[0] = np;
    }
    for (int i = tid; i < QPB * 128; i += 512) {
        int q = i >> 7, r = i & 127;
        qe_s[(q * 4 + (r >> 5)) * 36 + (r & 31)] = g_qe[(bh * SEQ + qidx_s[q]) * 128 + r];
    }
    __syncthreads();

    int np = np_s[0];
    int w = tid >> 5, lane = tid & 31;
    int qb = w * 4;
    int tql[4], qix[4], vsl[4];
    #pragma unroll
    for (int q = 0; q < 4; q++) {
        tql[q] = tq_s[qb + q];
        qix[q] = qidx_s[qb + q];
        vsl[q] = slot_s[tql[q]];
    }
    bool fast = (tql[0] == tql[1]) && (tql[1] == tql[2]) && (tql[2] == tql[3]);

    float m_run[4], l_run[4];
    unsigned long long acc2[4];
    #pragma unroll
    for (int q = 0; q < 4; q++) { m_run[q] = -INFINITY; l_run[q] = 0.f; acc2[q] = 0ull; }
    const float scale = 0.17677669529663687f;   // 1/sqrt(32)

    for (int kt = 0; kt < 16; kt++) {
        int kbase = kt * 32;
        for (int i = tid; i < 1024; i += 512) {
            int k = i >> 5, d = i & 31;
            k_s[k * 36 + d] = g_k[(bh * SEQ + kbase + k) * 32 + d];
        }
        for (int i = tid; i < np * 1024; i += 512) {
            int pl = i >> 10;
            int t = tlist[pl];
            int m = (i >> 5) & 31, kk = i & 31;
            ve_s[(pl * 32 + m) * 36 + kk] = g_ve2[(bh * 128 + t * 32 + m) * SEQ + kbase + kk];
        }
        __syncthreads();

        // ---- scores: lane = key ----
        int tk = tk_all[kbase + lane];
        int Kg = kbase + lane;
        unsigned long long sc2[4] = {0ull, 0ull, 0ull, 0ull};
        #pragma unroll
        for (int s = 0; s < 8; s++) {
            ulonglong2 k2 = *reinterpret_cast<const ulonglong2*>(&k_s[lane * 36 + s * 4]);
            #pragma unroll
            for (int q = 0; q < 4; q++) {
                ulonglong2 q2 = *reinterpret_cast<const ulonglong2*>(
                    &qe_s[((qb + q) * 4 + tk) * 36 + s * 4]);
                ffma2(sc2[q], q2.x, k2.x);
                ffma2(sc2[q], q2.y, k2.y);
            }
        }
        float corr[4];
        #pragma unroll
        for (int q = 0; q < 4; q++) {
            int c = (tql[q] != 0 && tk != 0) ? (tql[q] - 1) * 3 + tk : 0;
            float s = hadd2(sc2[q]) * scale + rp_s[c * 32 + bk_s[qix[q] - Kg + 511]]
                    + mask[(b * SEQ + qix[q]) * SEQ + Kg];
            float tm_ = s;
            #pragma unroll
            for (int o = 16; o; o >>= 1) tm_ = fmaxf(tm_, __shfl_xor_sync(0xffffffffu, tm_, o));
            float nm = fmaxf(m_run[q], tm_);
            corr[q] = __expf(m_run[q] - nm);
            m_run[q] = nm;
            float p = __expf(s - nm);
            float ps = p;
            #pragma unroll
            for (int o = 16; o; o >>= 1) ps += __shfl_xor_sync(0xffffffffu, ps, o);
            l_run[q] = l_run[q] * corr[q] + ps;
            p_s[(qb + q) * 32 + lane] = p;
        }
        __syncwarp();

        // ---- ctx: lane = output dim m ----
        #pragma unroll
        for (int q = 0; q < 4; q++) mulsc2(acc2[q], pack2(corr[q], corr[q]));
        if (fast) {
            const float* vb = &ve_s[(vsl[0] * 32 + lane) * 36];
            #pragma unroll
            for (int s = 0; s < 8; s++) {
                ulonglong2 v2 = *reinterpret_cast<const ulonglong2*>(&vb[s * 4]);
                #pragma unroll
                for (int q = 0; q < 4; q++) {
                    ulonglong2 p2 = *reinterpret_cast<const ulonglong2*>(
                        &p_s[(qb + q) * 32 + s * 4]);
                    ffma2(acc2[q], p2.x, v2.x);
                    ffma2(acc2[q], p2.y, v2.y);
                }
            }
        } else {
            #pragma unroll
            for (int q = 0; q < 4; q++) {
                const float* vb = &ve_s[(vsl[q] * 32 + lane) * 36];
                #pragma unroll
                for (int s = 0; s < 8; s++) {
                    ulonglong2 v2 = *reinterpret_cast<const ulonglong2*>(&vb[s * 4]);
                    ulonglong2 p2 = *reinterpret_cast<const ulonglong2*>(
                        &p_s[(qb + q) * 32 + s * 4]);
                    ffma2(acc2[q], p2.x, v2.x);
                    ffma2(acc2[q], p2.y, v2.y);
                }
            }
        }
        __syncthreads();
    }
    #pragma unroll
    for (int q = 0; q < 4; q++)
        g_ctx[(b * SEQ + qix[q]) * EMB + h * 32 + lane] = hadd2(acc2[q]) / l_run[q];
}

// -------- 6. residual + LayerNorm --------
__global__ void __launch_bounds__(256) ln_kernel(const float* __restrict__ x,
                                                 const float* __restrict__ gamma,
                                                 const float* __restrict__ beta,
                                                 float* __restrict__ out) {
    __shared__ float red[8];
    int row = blockIdx.x, tid = threadIdx.x;
    float v = g_ctx[row * 256 + tid] + x[row * 256 + tid];
    float s = v;
    #pragma unroll
    for (int o = 16; o; o >>= 1) s += __shfl_xor_sync(0xffffffffu, s, o);
    if ((tid & 31) == 0) red[tid >> 5] = s;
    __syncthreads();
    float tot = 0.0f;
    #pragma unroll
    for (int i = 0; i < 8; i++) tot += red[i];
    float mu = tot * (1.0f / 256.0f);
    float d = v - mu;
    float d2 = d * d;
    #pragma unroll
    for (int o = 16; o; o >>= 1) d2 += __shfl_xor_sync(0xffffffffu, d2, o);
    __syncthreads();
    if ((tid & 31) == 0) red[tid >> 5] = d2;
    __syncthreads();
    float var = 0.0f;
    #pragma unroll
    for (int i = 0; i < 8; i++) var += red[i];
    var *= (1.0f / 256.0f);
    out[row * 256 + tid] = d * rsqrtf(var + 1e-12f) * gamma[tid] + beta[tid];
}

extern "C" void kernel_launch(void* const* d_in, const int* in_sizes, int n_in,
                              void* d_out, int out_size) {
    (void)in_sizes; (void)n_in; (void)out_size;
    const float* x     = (const float*)d_in[0];
    const float* mask  = (const float*)d_in[1];
    const int*   ts    = (const int*)  d_in[2];
    const float* Wq    = (const float*)d_in[3];
    const float* Wk    = (const float*)d_in[4];
    const float* Wv    = (const float*)d_in[5];
    const float* W1    = (const float*)d_in[6];
    const float* a1    = (const float*)d_in[7];
    const float* W2    = (const float*)d_in[8];
    const float* a2    = (const float*)d_in[9];
    const float* rp    = (const float*)d_in[10];
    const float* gamma = (const float*)d_in[11];
    const float* beta  = (const float*)d_in[12];
    float* out = (float*)d_out;

    const int TR_SMEM  = 20672 * 4;   // 82688 B
    const int AT_SMEM  = 19024 * 4;   // 76096 B
    cudaFuncSetAttribute(transform2_kernel, cudaFuncAttributeMaxDynamicSharedMemorySize, TR_SMEM);
    cudaFuncSetAttribute(attn_kernel,       cudaFuncAttributeMaxDynamicSharedMemorySize, AT_SMEM);

    setup_kernel<<<166, 1024>>>(W1, a1, W2, a2, ts);
    proj2_kernel<<<dim3(LCAP / 16, 3), 256>>>(x, ts, Wq, Wk, Wv);
    transform2_kernel<<<dim3(32, 8, 2), 128, TR_SMEM>>>(ts);
    attn_kernel<<<dim3(SEQ / QPB, HEADS, BATCH), 512, AT_SMEM>>>(mask, ts, rp);
    ln_kernel<<<NTOK, 256>>>(x, gamma, beta, out);
}